// round 4
// baseline (speedup 1.0000x reference)
#include <cuda_runtime.h>

// Brain connectomic GCN: 2048 independent graphs x 100 nodes x 2000 edges.
// One CTA per graph; 2 CTAs/SM (smem 97.7 KB). Layer-1 weights read from
// global (L2-resident, shared by all CTAs); everything else staged in smem.
//
// Pipeline per graph:
//   h  = x @ (row<50 ? W_l1 : W_r1)                 [100,64]
//   h1 = lrelu(aggr_hemi(h, dinv1) + b1(row))       [100,64]  (h1 overwrites x)
//   p2 = h1 @ (row<50 ? W_l2 : W_r2)                [100,20]
//   h2 = lrelu(aggr_hemi(p2, dinv1) + b2(row))      [100,20]
//   p3 = h2 @ W_g1                                  [100,20]
//   h3 = lrelu(aggr_all(p3, dinv3) + bg)            [100,20]
//   out[g] = mean_rows(h3)                          [20]
//
// aggr(h)[d] = h[d]*dinv[d]^2 + sum_{e: dst=d} h[src]*dinv[src]*w*dinv[d]
// deg[d] = 1 + sum of (masked) edge weights into d; dinv = rsqrt(deg).
//
// NOTE: edge_index is int32 (JAX x64 disabled -> jnp.int64 materializes as i32).

#define NPG 100
#define EPG 2000

// ---- shared memory layout (bytes) ----
#define OFF_SX    0        // 10000 f : x tile; h1 aliases first 6400 f after GEMM1
#define OFF_SH    40000    // 6400 f  : x@W pre-agg; later p2@0 / h2@2000 / p3@4000
#define OFF_SPK   65600    // 2000 i32 sorted packed edges (src | dst<<8 | hemi<<16)
#define OFF_SEW   73600    // 2000 f   sorted edge weights
#define OFF_W2L   81600    // 1280 f
#define OFF_W2R   86720    // 1280 f
#define OFF_WG    91840    // 400 f
#define OFF_SB    93440    // 192 f : b1l[0..63] b1r[64..127] b2l@128 b2r@148 bg@168
#define OFF_CNT   94208    // 100 i32
#define OFF_START 94608    // 101 i32 (+pad)
#define OFF_CUR   95024    // 100 i32
#define OFF_DEG1  95424    // 100 f
#define OFF_DEG3  95824    // 100 f
#define OFF_DI1   96224    // 100 f
#define OFF_DI3   96624    // 100 f
#define OFF_PART  97024    // 160 f (8 warps x 20)
#define SMEM_TOTAL 97664

__device__ __forceinline__ float lrelu(float v) {
    return v > 0.f ? v : 0.01f * v;
}

extern __shared__ char S[];

__global__ void __launch_bounds__(256, 2) gcn_fused_kernel(
    const float* __restrict__ x,   const float* __restrict__ ea,
    const float* __restrict__ Wl1, const float* __restrict__ bl1,
    const float* __restrict__ Wr1, const float* __restrict__ br1,
    const float* __restrict__ Wl2, const float* __restrict__ bl2,
    const float* __restrict__ Wr2, const float* __restrict__ br2,
    const float* __restrict__ Wg,  const float* __restrict__ bg,
    const int* __restrict__ eidx, long long Etot,
    float* __restrict__ out)
{
    float* sx   = (float*)(S + OFF_SX);
    float* sh   = (float*)(S + OFF_SH);
    int*   spk  = (int*)  (S + OFF_SPK);
    float* sew  = (float*)(S + OFF_SEW);
    float* sW2l = (float*)(S + OFF_W2L);
    float* sW2r = (float*)(S + OFF_W2R);
    float* sWg  = (float*)(S + OFF_WG);
    float* sb   = (float*)(S + OFF_SB);
    int*   scnt = (int*)  (S + OFF_CNT);
    int*   sstart=(int*)  (S + OFF_START);
    int*   scur = (int*)  (S + OFF_CUR);
    float* sdeg1= (float*)(S + OFF_DEG1);
    float* sdeg3= (float*)(S + OFF_DEG3);
    float* sdi1 = (float*)(S + OFF_DI1);
    float* sdi3 = (float*)(S + OFF_DI3);
    float* spart= (float*)(S + OFF_PART);
    // aliases: h1 lives in the x tile after GEMM1; p2/h2/p3 live in sh after
    // the layer-1 aggregation consumes it.
    float* h1 = sx;          // 6400 f
    float* p2 = sh;          // 2000 f
    float* h2 = sh + 2000;   // 2000 f
    float* p3 = sh + 4000;   // 2000 f

    const int g    = blockIdx.x;
    const int tid  = threadIdx.x;
    const int w    = tid >> 5;
    const int lane = tid & 31;

    // row ownership: warps 0-3 -> left rows, 4-7 -> right rows
    const int hw    = w & 3;
    const int base0 = (w < 4) ? 0 : 50;
    const int nr    = (hw < 2) ? 13 : 12;   // rows d = base0 + hw + 4*t

    // ---------------- phase 0: stage x, small weights, biases -------------
    {
        const float4* xg = (const float4*)(x + (size_t)g * NPG * 100);
        float4* d4 = (float4*)sx;
        for (int i = tid; i < 2500; i += 256) d4[i] = xg[i];

        const float4* s4;
        s4 = (const float4*)Wl2; d4 = (float4*)sW2l;
        for (int i = tid; i < 320; i += 256) d4[i] = s4[i];
        s4 = (const float4*)Wr2; d4 = (float4*)sW2r;
        for (int i = tid; i < 320; i += 256) d4[i] = s4[i];
        s4 = (const float4*)Wg; d4 = (float4*)sWg;
        for (int i = tid; i < 100; i += 256) d4[i] = s4[i];

        if (tid < 64) { sb[tid] = bl1[tid]; sb[64 + tid] = br1[tid]; }
        if (tid < 20) { sb[128 + tid] = bl2[tid]; sb[148 + tid] = br2[tid];
                        sb[168 + tid] = bg[tid]; }
        if (tid < 100) { scnt[tid] = 0; sdeg1[tid] = 1.0f; sdeg3[tid] = 1.0f; }
    }
    __syncthreads();

    // ---------------- phase 1: load edges -> regs, count + degree ---------
    int   myPk[8];
    float myW[8];
    {
        const size_t gbase = (size_t)g * EPG;
        const int    noff  = g * NPG;
        #pragma unroll
        for (int r = 0; r < 8; ++r) {
            int e = tid + 256 * r;
            if (e < EPG) {
                int ls = eidx[gbase + e] - noff;
                int ld = eidx[(size_t)Etot + gbase + e] - noff;
                float wv = ea[gbase + e];
                int hemi = ((ls < 50) == (ld < 50)) ? 1 : 0;
                myPk[r] = ls | (ld << 8) | (hemi << 16);
                myW[r]  = wv;
                atomicAdd(&scnt[ld], 1);
                atomicAdd(&sdeg3[ld], wv);
                if (hemi) atomicAdd(&sdeg1[ld], wv);
            } else {
                myPk[r] = -1; myW[r] = 0.f;
            }
        }
    }
    __syncthreads();

    // ---------------- phase 2: prefix sum (warp 0) + dinv (other threads) -
    if (w == 0) {
        int c[4];
        int tot = 0;
        #pragma unroll
        for (int i = 0; i < 4; ++i) {
            int b = lane * 4 + i;
            c[i] = (b < 100) ? scnt[b] : 0;
            tot += c[i];
        }
        int incl = tot;
        #pragma unroll
        for (int off = 1; off < 32; off <<= 1) {
            int v = __shfl_up_sync(0xffffffffu, incl, off);
            if (lane >= off) incl += v;
        }
        int run = incl - tot;   // exclusive prefix
        #pragma unroll
        for (int i = 0; i < 4; ++i) {
            int b = lane * 4 + i;
            if (b < 100) { sstart[b] = run; scur[b] = run; run += c[i]; }
        }
        if (lane == 31) sstart[100] = run;
    } else {
        int i = tid - 32;
        if (i < 100)        sdi1[i]       = rsqrtf(sdeg1[i]);
        else if (i < 200)   sdi3[i - 100] = rsqrtf(sdeg3[i - 100]);
    }
    __syncthreads();

    // ---------------- phase 3: scatter edges into dst buckets -------------
    #pragma unroll
    for (int r = 0; r < 8; ++r) {
        if (myPk[r] >= 0) {
            int ld = (myPk[r] >> 8) & 0xff;
            int pos = atomicAdd(&scur[ld], 1);
            spk[pos] = myPk[r];
            sew[pos] = myW[r];
        }
    }
    __syncthreads();

    // ---------------- phase 4: GEMM1  sh = x @ W(hemi)  [100,64] ----------
    // Weights read directly from global: identical across all CTAs -> L2.
    {
        const float* Wb = (w < 4) ? Wl1 : Wr1;
        const int col = 2 * lane;
        float2 acc[13];
        #pragma unroll
        for (int r = 0; r < 13; ++r) acc[r] = make_float2(0.f, 0.f);
        for (int k = 0; k < 100; k += 4) {
            float2 w0 = __ldg((const float2*)(Wb + (k + 0) * 64 + col));
            float2 w1 = __ldg((const float2*)(Wb + (k + 1) * 64 + col));
            float2 w2 = __ldg((const float2*)(Wb + (k + 2) * 64 + col));
            float2 w3 = __ldg((const float2*)(Wb + (k + 3) * 64 + col));
            #pragma unroll
            for (int r = 0; r < 13; ++r) {
                if (r < nr) {
                    int d = base0 + hw + 4 * r;
                    float4 xv = *(const float4*)(sx + d * 100 + k);
                    acc[r].x = fmaf(xv.x, w0.x, acc[r].x);
                    acc[r].y = fmaf(xv.x, w0.y, acc[r].y);
                    acc[r].x = fmaf(xv.y, w1.x, acc[r].x);
                    acc[r].y = fmaf(xv.y, w1.y, acc[r].y);
                    acc[r].x = fmaf(xv.z, w2.x, acc[r].x);
                    acc[r].y = fmaf(xv.z, w2.y, acc[r].y);
                    acc[r].x = fmaf(xv.w, w3.x, acc[r].x);
                    acc[r].y = fmaf(xv.w, w3.y, acc[r].y);
                }
            }
        }
        #pragma unroll
        for (int r = 0; r < 13; ++r) {
            if (r < nr) {
                int d = base0 + hw + 4 * r;
                *(float2*)(sh + d * 64 + col) = acc[r];
            }
        }
    }
    __syncthreads();

    // ---------------- phase 5: aggregate layer1 -> h1 (lrelu) -------------
    // Reads sh (pre-agg), writes h1 into the (dead) x tile.
    for (int t = 0; t < nr; ++t) {
        int d = base0 + hw + 4 * t;
        float dv = sdi1[d];
        float self = dv * dv;
        float a0 = sh[d * 64 + lane] * self;
        float a1 = sh[d * 64 + lane + 32] * self;
        int e0 = sstart[d], e1 = sstart[d + 1];
        for (int e = e0; e < e1; ++e) {
            int pk = spk[e];
            if (pk & (1 << 16)) {
                int ls = pk & 0xff;
                float nrm = sdi1[ls] * sew[e] * dv;
                a0 = fmaf(sh[ls * 64 + lane],      nrm, a0);
                a1 = fmaf(sh[ls * 64 + lane + 32], nrm, a1);
            }
        }
        int bb = (d < 50) ? 0 : 64;
        h1[d * 64 + lane]      = lrelu(a0 + sb[bb + lane]);
        h1[d * 64 + lane + 32] = lrelu(a1 + sb[bb + lane + 32]);
    }
    __syncthreads();

    // ---------------- phase 6: GEMM2  p2 = h1 @ W2(hemi)  [100,20] --------
    // Writes p2 into the (dead) sh region.
    if (lane < 20) {
        const float* W2 = (w < 4) ? sW2l : sW2r;
        for (int t = 0; t < nr; ++t) {
            int d = base0 + hw + 4 * t;
            float acc = 0.f;
            for (int k = 0; k < 64; k += 4) {
                float4 hv = *(const float4*)(h1 + d * 64 + k);
                acc = fmaf(hv.x, W2[(k + 0) * 20 + lane], acc);
                acc = fmaf(hv.y, W2[(k + 1) * 20 + lane], acc);
                acc = fmaf(hv.z, W2[(k + 2) * 20 + lane], acc);
                acc = fmaf(hv.w, W2[(k + 3) * 20 + lane], acc);
            }
            p2[d * 20 + lane] = acc;
        }
    }
    __syncthreads();

    // ---------------- phase 7: aggregate layer2 -> h2 (lrelu) -------------
    if (lane < 20) {
        for (int t = 0; t < nr; ++t) {
            int d = base0 + hw + 4 * t;
            float dv = sdi1[d];
            float a = p2[d * 20 + lane] * dv * dv;
            int e0 = sstart[d], e1 = sstart[d + 1];
            for (int e = e0; e < e1; ++e) {
                int pk = spk[e];
                if (pk & (1 << 16)) {
                    int ls = pk & 0xff;
                    float nrm = sdi1[ls] * sew[e] * dv;
                    a = fmaf(p2[ls * 20 + lane], nrm, a);
                }
            }
            int bb = (d < 50) ? 128 : 148;
            h2[d * 20 + lane] = lrelu(a + sb[bb + lane]);
        }
    }
    __syncthreads();

    // ---------------- phase 8: GEMM3  p3 = h2 @ Wg  [100,20] --------------
    if (lane < 20) {
        for (int t = 0; t < nr; ++t) {
            int d = base0 + hw + 4 * t;
            float acc = 0.f;
            #pragma unroll
            for (int k = 0; k < 20; ++k)
                acc = fmaf(h2[d * 20 + k], sWg[k * 20 + lane], acc);
            p3[d * 20 + lane] = acc;
        }
    }
    __syncthreads();

    // ---------------- phase 9: aggregate layer3 (all edges) + pool --------
    {
        float pool = 0.f;
        if (lane < 20) {
            for (int t = 0; t < nr; ++t) {
                int d = base0 + hw + 4 * t;
                float dv = sdi3[d];
                float a = p3[d * 20 + lane] * dv * dv;
                int e0 = sstart[d], e1 = sstart[d + 1];
                for (int e = e0; e < e1; ++e) {
                    int pk = spk[e];
                    int ls = pk & 0xff;
                    float nrm = sdi3[ls] * sew[e] * dv;
                    a = fmaf(p3[ls * 20 + lane], nrm, a);
                }
                pool += lrelu(a + sb[168 + lane]);
            }
            spart[w * 20 + lane] = pool;
        }
    }
    __syncthreads();

    if (tid < 20) {
        float s = 0.f;
        #pragma unroll
        for (int ww = 0; ww < 8; ++ww) s += spart[ww * 20 + tid];
        out[(size_t)g * 20 + tid] = s * 0.01f;   // mean over 100 nodes
    }
}

extern "C" void kernel_launch(void* const* d_in, const int* in_sizes, int n_in,
                              void* d_out, int out_size)
{
    (void)n_in;
    const long long Etot = (long long)in_sizes[1];   // total edges
    const int numGraphs = (int)(Etot / EPG);

    cudaFuncSetAttribute(gcn_fused_kernel,
                         cudaFuncAttributeMaxDynamicSharedMemorySize, SMEM_TOTAL);

    gcn_fused_kernel<<<numGraphs, 256, SMEM_TOTAL>>>(
        (const float*)d_in[0],  (const float*)d_in[1],
        (const float*)d_in[2],  (const float*)d_in[3],
        (const float*)d_in[4],  (const float*)d_in[5],
        (const float*)d_in[6],  (const float*)d_in[7],
        (const float*)d_in[8],  (const float*)d_in[9],
        (const float*)d_in[10], (const float*)d_in[11],
        (const int*)d_in[12], Etot,
        (float*)d_out);
    (void)out_size;
}

// round 6
// speedup vs baseline: 1.5655x; 1.5655x over previous
#include <cuda_runtime.h>

// Brain connectomic GCN: 2048 independent graphs x 100 nodes x 2000 edges.
// One CTA per graph, 2 CTAs/SM. Edge list counting-sorted by dst with
// same-hemisphere edges first in each bucket; per-edge norms precomputed.
//
//   h   = x @ (row<50 ? W_l1 : W_r1)           [100,64]  (f32x2 GEMM, x from gmem)
//   h1  = lrelu(agg_hemi(h) + b1)              [100,64]
//   p2  = h1 @ (row<50 ? W_l2 : W_r2)          [100,20]
//   h2  = lrelu(agg_hemi(p2) + b2)             [100,20]
//   p3  = h2 @ W_g1                            [100,20]
//   h3  = lrelu(agg_all(p3) + bg)              [100,20]
//   out[g] = mean_rows(h3)                     [20]
//
// agg(h)[d] = h[d]*dinv[d]^2 + sum_e nrm[e]*h[src[e]],  nrm = dinv[s]*w*dinv[d]
// deg[d] = 1 + sum of (masked) in-edge weights; dinv = rsqrt(deg).
// edge_index is int32 (JAX x64 disabled).

#define NPG 100
#define EPG 2000

// ---- shared memory layout (bytes) ----
#define OFF_SH    0        // 6400 f : pre-agg h; later p2@0 / h2@2000 / p3@4000
#define OFF_SH1   25600    // 6400 f : h1
#define OFF_SE1   51200    // 2000 int2 : scatter tmp {pk,w}; then {src,nrm1} in hemi slots
#define OFF_SE3   67200    // 2000 int2 : {src,nrm3}
#define OFF_W2L   83200    // 1280 f
#define OFF_W2R   88320    // 1280 f
#define OFF_WG    93440    // 400 f
#define OFF_SB    95040    // 192 f : b1l[0..63] b1r[64..127] b2l@128 b2r@148 bg@168
#define OFF_CNT   95808    // 100 i32 packed: hemi count low16 | cross count high16
#define OFF_START 96208    // 101 i32 (+pad)
#define OFF_HEND  96624    // 100 i32
#define OFF_CURH  97024    // 100 i32
#define OFF_CURC  97424    // 100 i32
#define OFF_DI1   97824    // 100 f
#define OFF_DI3   98224    // 100 f
#define OFF_PART  98624    // 160 f (8 warps x 20)
#define SMEM_TOTAL 99264

__device__ __forceinline__ float lrelu(float v) {
    return v > 0.f ? v : 0.01f * v;
}

extern __shared__ char S[];

__global__ void __launch_bounds__(256, 2) gcn_fused_kernel(
    const float* __restrict__ x,   const float* __restrict__ ea,
    const float* __restrict__ Wl1, const float* __restrict__ bl1,
    const float* __restrict__ Wr1, const float* __restrict__ br1,
    const float* __restrict__ Wl2, const float* __restrict__ bl2,
    const float* __restrict__ Wr2, const float* __restrict__ br2,
    const float* __restrict__ Wg,  const float* __restrict__ bg,
    const int* __restrict__ eidx, long long Etot,
    float* __restrict__ out)
{
    float* sh   = (float*)(S + OFF_SH);
    float* sh1  = (float*)(S + OFF_SH1);
    int2*  se1  = (int2*) (S + OFF_SE1);
    int2*  se3  = (int2*) (S + OFF_SE3);
    float* sW2l = (float*)(S + OFF_W2L);
    float* sW2r = (float*)(S + OFF_W2R);
    float* sWg  = (float*)(S + OFF_WG);
    float* sb   = (float*)(S + OFF_SB);
    int*   scnt = (int*)  (S + OFF_CNT);
    int*   sstart=(int*)  (S + OFF_START);
    int*   shend= (int*)  (S + OFF_HEND);
    int*   scurh= (int*)  (S + OFF_CURH);
    int*   scurc= (int*)  (S + OFF_CURC);
    float* sdi1 = (float*)(S + OFF_DI1);
    float* sdi3 = (float*)(S + OFF_DI3);
    float* spart= (float*)(S + OFF_PART);
    // aliases into the (dead after agg1) pre-agg region
    float* p2 = sh;          // 2000 f
    float* h2 = sh + 2000;   // 2000 f
    float* p3 = sh + 4000;   // 2000 f

    const int g    = blockIdx.x;
    const int tid  = threadIdx.x;
    const int w    = tid >> 5;
    const int lane = tid & 31;

    // row ownership: warps 0-3 -> left rows, 4-7 -> right rows
    const int hw    = w & 3;
    const int base0 = (w < 4) ? 0 : 50;
    const int nr    = (hw < 2) ? 13 : 12;   // rows d = base0 + hw + 4*t

    // ---------------- P0: stage small weights, biases; init counters ------
    {
        const float4* s4; float4* d4;
        s4 = (const float4*)Wl2; d4 = (float4*)sW2l;
        for (int i = tid; i < 320; i += 256) d4[i] = s4[i];
        s4 = (const float4*)Wr2; d4 = (float4*)sW2r;
        for (int i = tid; i < 320; i += 256) d4[i] = s4[i];
        s4 = (const float4*)Wg; d4 = (float4*)sWg;
        for (int i = tid; i < 100; i += 256) d4[i] = s4[i];

        if (tid < 64) { sb[tid] = bl1[tid]; sb[64 + tid] = br1[tid]; }
        if (tid < 20) { sb[128 + tid] = bl2[tid]; sb[148 + tid] = br2[tid];
                        sb[168 + tid] = bg[tid]; }
        if (tid < 100) scnt[tid] = 0;
    }
    __syncthreads();

    // ---------------- P1: load edges -> regs, packed hemi/cross count -----
    int   myPk[8];
    float myW[8];
    {
        const size_t gbase = (size_t)g * EPG;
        const int    noff  = g * NPG;
        #pragma unroll
        for (int r = 0; r < 8; ++r) {
            int e = tid + 256 * r;
            if (e < EPG) {
                int ls = eidx[gbase + e] - noff;
                int ld = eidx[(size_t)Etot + gbase + e] - noff;
                float wv = ea[gbase + e];
                int hemi = ((ls < 50) == (ld < 50)) ? 1 : 0;
                myPk[r] = ls | (ld << 8) | (hemi << 16);
                myW[r]  = wv;
                atomicAdd(&scnt[ld], hemi ? 1 : 0x10000);
            } else {
                myPk[r] = -1; myW[r] = 0.f;
            }
        }
    }
    __syncthreads();

    // ---------------- P2: prefix sum over buckets (warp 0) ----------------
    if (w == 0) {
        int hc[4], tc[4];
        int tot = 0;
        #pragma unroll
        for (int i = 0; i < 4; ++i) {
            int b = lane * 4 + i;
            int v = (b < 100) ? scnt[b] : 0;
            hc[i] = v & 0xffff;
            tc[i] = hc[i] + (v >> 16);
            tot += tc[i];
        }
        int incl = tot;
        #pragma unroll
        for (int off = 1; off < 32; off <<= 1) {
            int v = __shfl_up_sync(0xffffffffu, incl, off);
            if (lane >= off) incl += v;
        }
        int run = incl - tot;   // exclusive prefix
        #pragma unroll
        for (int i = 0; i < 4; ++i) {
            int b = lane * 4 + i;
            if (b < 100) {
                sstart[b] = run;
                shend[b]  = run + hc[i];
                scurh[b]  = run;
                scurc[b]  = run + hc[i];
                run += tc[i];
            }
        }
        if (lane == 31) sstart[100] = run;
    }
    __syncthreads();

    // ---------------- P3: scatter edges (hemi first within bucket) --------
    #pragma unroll
    for (int r = 0; r < 8; ++r) {
        if (myPk[r] >= 0) {
            int ld = (myPk[r] >> 8) & 0xff;
            int* cur = (myPk[r] & (1 << 16)) ? scurh : scurc;
            int pos = atomicAdd(&cur[ld], 1);
            se1[pos] = make_int2(myPk[r], __float_as_int(myW[r]));
        }
    }
    __syncthreads();

    // ---------------- P4: degrees via bucket scan -> dinv -----------------
    if (tid < 100) {
        int s = sstart[tid], he = shend[tid], e1 = sstart[tid + 1];
        float dg1 = 1.f, dg3 = 1.f;
        for (int e = s; e < e1; ++e) {
            float wv = __int_as_float(se1[e].y);
            dg3 += wv;
            if (e < he) dg1 += wv;
        }
        sdi1[tid] = rsqrtf(dg1);
        sdi3[tid] = rsqrtf(dg3);
    }
    __syncthreads();

    // ---------------- P5: per-edge norm precompute ------------------------
    #pragma unroll
    for (int r = 0; r < 8; ++r) {
        int e = tid + 256 * r;
        if (e < EPG) {
            int2 ed = se1[e];
            int pk = ed.x;
            float wv = __int_as_float(ed.y);
            int ls = pk & 0xff;
            int ld = (pk >> 8) & 0xff;
            float n3 = sdi3[ls] * wv * sdi3[ld];
            se3[e] = make_int2(ls, __float_as_int(n3));
            if (pk & (1 << 16)) {
                float n1 = sdi1[ls] * wv * sdi1[ld];
                se1[e] = make_int2(ls, __float_as_int(n1));
            }
        }
    }
    __syncthreads();

    // ---------------- P6: GEMM1  sh = x @ W(hemi)  [100,64] ---------------
    // f32x2 packed FMA, k-parity pairing. x and W read from global
    // (W shared by all CTAs -> L2; x elements each used exactly once).
    {
        const float* Wb = (w < 4) ? Wl1 : Wr1;
        const float* xg = x + (size_t)g * NPG * 100;
        unsigned long long accA[13], accB[13];
        #pragma unroll
        for (int r = 0; r < 13; ++r) { accA[r] = 0ull; accB[r] = 0ull; }
        for (int k = 0; k < 100; k += 2) {
            float wa0 = __ldg(Wb + k * 64 + lane);
            float wa1 = __ldg(Wb + (k + 1) * 64 + lane);
            float wb0 = __ldg(Wb + k * 64 + lane + 32);
            float wb1 = __ldg(Wb + (k + 1) * 64 + lane + 32);
            unsigned long long wA, wB;
            asm("mov.b64 %0,{%1,%2};" : "=l"(wA) : "f"(wa0), "f"(wa1));
            asm("mov.b64 %0,{%1,%2};" : "=l"(wB) : "f"(wb0), "f"(wb1));
            #pragma unroll
            for (int r = 0; r < 13; ++r) {
                if (r < nr) {
                    int d = base0 + hw + 4 * r;
                    unsigned long long xd =
                        __ldg((const unsigned long long*)(xg + d * 100 + k));
                    asm("fma.rn.f32x2 %0,%1,%2,%0;" : "+l"(accA[r]) : "l"(xd), "l"(wA));
                    asm("fma.rn.f32x2 %0,%1,%2,%0;" : "+l"(accB[r]) : "l"(xd), "l"(wB));
                }
            }
        }
        #pragma unroll
        for (int r = 0; r < 13; ++r) {
            if (r < nr) {
                int d = base0 + hw + 4 * r;
                float2 a = *(float2*)&accA[r];
                float2 b = *(float2*)&accB[r];
                sh[d * 64 + lane]      = a.x + a.y;
                sh[d * 64 + lane + 32] = b.x + b.y;
            }
        }
    }
    __syncthreads();

    // ---------------- P7: aggregate layer1 -> h1 (hemi edges only) --------
    for (int t = 0; t < nr; ++t) {
        int d = base0 + hw + 4 * t;
        float dv = sdi1[d];
        float self = dv * dv;
        float a0 = sh[d * 64 + lane] * self;
        float a1 = sh[d * 64 + lane + 32] * self;
        int e0 = sstart[d], e1 = shend[d];
        #pragma unroll 2
        for (int e = e0; e < e1; ++e) {
            int2 ed = se1[e];                       // broadcast {src, nrm1}
            float nm = __int_as_float(ed.y);
            a0 = fmaf(sh[ed.x * 64 + lane],      nm, a0);
            a1 = fmaf(sh[ed.x * 64 + lane + 32], nm, a1);
        }
        int bb = (d < 50) ? 0 : 64;
        sh1[d * 64 + lane]      = lrelu(a0 + sb[bb + lane]);
        sh1[d * 64 + lane + 32] = lrelu(a1 + sb[bb + lane + 32]);
    }
    __syncthreads();

    // ---------------- P8: GEMM2  p2 = h1 @ W2(hemi)  [100,20] -------------
    // W2 chunk-hoisted to registers: k in 4 chunks of 16.
    if (lane < 20) {
        const float* W2 = (w < 4) ? sW2l : sW2r;
        float acc[13];
        #pragma unroll
        for (int r = 0; r < 13; ++r) acc[r] = 0.f;
        for (int kc = 0; kc < 64; kc += 16) {
            float wreg[16];
            #pragma unroll
            for (int i = 0; i < 16; ++i) wreg[i] = W2[(kc + i) * 20 + lane];
            for (int t = 0; t < nr; ++t) {
                int d = base0 + hw + 4 * t;
                const float* hr = sh1 + d * 64 + kc;
                #pragma unroll
                for (int i = 0; i < 16; i += 4) {
                    float4 hv = *(const float4*)(hr + i);
                    acc[t] = fmaf(hv.x, wreg[i + 0], acc[t]);
                    acc[t] = fmaf(hv.y, wreg[i + 1], acc[t]);
                    acc[t] = fmaf(hv.z, wreg[i + 2], acc[t]);
                    acc[t] = fmaf(hv.w, wreg[i + 3], acc[t]);
                }
            }
        }
        for (int t = 0; t < nr; ++t) {
            int d = base0 + hw + 4 * t;
            p2[d * 20 + lane] = acc[t];
        }
    }
    __syncthreads();

    // ---------------- P9: aggregate layer2 -> h2 (hemi edges only) --------
    if (lane < 20) {
        for (int t = 0; t < nr; ++t) {
            int d = base0 + hw + 4 * t;
            float dv = sdi1[d];
            float a = p2[d * 20 + lane] * dv * dv;
            int e0 = sstart[d], e1 = shend[d];
            #pragma unroll 2
            for (int e = e0; e < e1; ++e) {
                int2 ed = se1[e];
                a = fmaf(p2[ed.x * 20 + lane], __int_as_float(ed.y), a);
            }
            int bb = (d < 50) ? 128 : 148;
            h2[d * 20 + lane] = lrelu(a + sb[bb + lane]);
        }
    }
    __syncthreads();

    // ---------------- P10: GEMM3  p3 = h2 @ Wg  [100,20] ------------------
    if (lane < 20) {
        float wg[20];
        #pragma unroll
        for (int k = 0; k < 20; ++k) wg[k] = sWg[k * 20 + lane];
        for (int t = 0; t < nr; ++t) {
            int d = base0 + hw + 4 * t;
            float acc = 0.f;
            #pragma unroll
            for (int k = 0; k < 20; ++k)
                acc = fmaf(h2[d * 20 + k], wg[k], acc);
            p3[d * 20 + lane] = acc;
        }
    }
    __syncthreads();

    // ---------------- P11: aggregate layer3 (all edges) + pool ------------
    {
        float pool = 0.f;
        if (lane < 20) {
            for (int t = 0; t < nr; ++t) {
                int d = base0 + hw + 4 * t;
                float dv = sdi3[d];
                float a = p3[d * 20 + lane] * dv * dv;
                int e0 = sstart[d], e1 = sstart[d + 1];
                #pragma unroll 2
                for (int e = e0; e < e1; ++e) {
                    int2 ed = se3[e];
                    a = fmaf(p3[ed.x * 20 + lane], __int_as_float(ed.y), a);
                }
                pool += lrelu(a + sb[168 + lane]);
            }
            spart[w * 20 + lane] = pool;
        }
    }
    __syncthreads();

    if (tid < 20) {
        float s = 0.f;
        #pragma unroll
        for (int ww = 0; ww < 8; ++ww) s += spart[ww * 20 + tid];
        out[(size_t)g * 20 + tid] = s * 0.01f;   // mean over 100 nodes
    }
}

extern "C" void kernel_launch(void* const* d_in, const int* in_sizes, int n_in,
                              void* d_out, int out_size)
{
    (void)n_in;
    const long long Etot = (long long)in_sizes[1];   // total edges
    const int numGraphs = (int)(Etot / EPG);

    cudaFuncSetAttribute(gcn_fused_kernel,
                         cudaFuncAttributeMaxDynamicSharedMemorySize, SMEM_TOTAL);

    gcn_fused_kernel<<<numGraphs, 256, SMEM_TOTAL>>>(
        (const float*)d_in[0],  (const float*)d_in[1],
        (const float*)d_in[2],  (const float*)d_in[3],
        (const float*)d_in[4],  (const float*)d_in[5],
        (const float*)d_in[6],  (const float*)d_in[7],
        (const float*)d_in[8],  (const float*)d_in[9],
        (const float*)d_in[10], (const float*)d_in[11],
        (const int*)d_in[12], Etot,
        (float*)d_out);
    (void)out_size;
}

// round 7
// speedup vs baseline: 1.5741x; 1.0055x over previous
#include <cuda_runtime.h>

// Brain connectomic GCN: 2048 independent graphs x 100 nodes x 2000 edges.
// One CTA per graph, 3 CTAs/SM (smem 71.4KB, <=85 regs). Edges counting-sorted
// by dst, same-hemisphere first per bucket; per-edge norms precomputed and
// packed into 4 bytes: fp32 norm with src index in the low 7 mantissa bits
// (max 1.5e-5 relative perturbation; tolerance is 1e-3).
//
//   h   = x @ (row<50 ? W_l1 : W_r1)           [100,64]  (f32x2 GEMM, x from gmem)
//   h1  = lrelu(agg_hemi(h) + b1)              [100,64]
//   p2  = h1 @ (row<50 ? W_l2 : W_r2)          [100,20]
//   h2  = lrelu(agg_hemi(p2) + b2)             [100,20]
//   p3  = h2 @ W_g1                            [100,20]
//   h3  = lrelu(agg_all(p3) + bg)              [100,20]
//   out[g] = mean_rows(h3)                     [20]
//
// agg(h)[d] = h[d]*dinv[d]^2 + sum_e nrm[e]*h[src[e]],  nrm = dinv[s]*w*dinv[d]
// deg[d] = 1 + sum of (masked) in-edge weights; dinv = rsqrt(deg).
// edge_index is int32 (JAX x64 disabled).

#define NPG 100
#define EPG 2000

// ---- shared memory layout (bytes), total 71416 <= 72KB alloc ----
#define OFF_SH    0        // 6400 f : pre-agg h; later p2@0 / h2@2000 / p3@4000
#define OFF_SH1   25600    // 6400 f : h1
#define OFF_SEA   51200    // 2000 i32 : pk during sort; packed{nrm1,src} in hemi slots
#define OFF_SEB   59200    // 2000 i32 : w during sort; packed{nrm3,src} after
#define OFF_SB    67200    // 192 f : b1l[0..63] b1r[64..127] b2l@128 b2r@148 bg@168
#define OFF_CNT   67968    // 100 i32 packed: hemi count low16 | cross count high16
#define OFF_START 68368    // 101 i32 (+pad)
#define OFF_HEND  68776    // 100 i32
#define OFF_CURH  69176    // 100 i32
#define OFF_CURC  69576    // 100 i32
#define OFF_DI1   69976    // 100 f
#define OFF_DI3   70376    // 100 f
#define OFF_PART  70776    // 160 f (8 warps x 20)
#define SMEM_TOTAL 71416

__device__ __forceinline__ float lrelu(float v) {
    return v > 0.f ? v : 0.01f * v;
}

// pack: fp32 norm with src (<128) replacing the low 7 mantissa bits
__device__ __forceinline__ int pack_ns(float nrm, int src) {
    return (__float_as_int(nrm) & ~0x7F) | src;
}

extern __shared__ char S[];

__global__ void __launch_bounds__(256, 3) gcn_fused_kernel(
    const float* __restrict__ x,   const float* __restrict__ ea,
    const float* __restrict__ Wl1, const float* __restrict__ bl1,
    const float* __restrict__ Wr1, const float* __restrict__ br1,
    const float* __restrict__ Wl2, const float* __restrict__ bl2,
    const float* __restrict__ Wr2, const float* __restrict__ br2,
    const float* __restrict__ Wg,  const float* __restrict__ bg,
    const int* __restrict__ eidx, long long Etot,
    float* __restrict__ out)
{
    float* sh   = (float*)(S + OFF_SH);
    float* sh1  = (float*)(S + OFF_SH1);
    int*   seA  = (int*)  (S + OFF_SEA);
    int*   seB  = (int*)  (S + OFF_SEB);
    float* sb   = (float*)(S + OFF_SB);
    int*   scnt = (int*)  (S + OFF_CNT);
    int*   sstart=(int*)  (S + OFF_START);
    int*   shend= (int*)  (S + OFF_HEND);
    int*   scurh= (int*)  (S + OFF_CURH);
    int*   scurc= (int*)  (S + OFF_CURC);
    float* sdi1 = (float*)(S + OFF_DI1);
    float* sdi3 = (float*)(S + OFF_DI3);
    float* spart= (float*)(S + OFF_PART);
    // aliases into the (dead after agg1) pre-agg region
    float* p2 = sh;          // 2000 f
    float* h2 = sh + 2000;   // 2000 f
    float* p3 = sh + 4000;   // 2000 f

    const int g    = blockIdx.x;
    const int tid  = threadIdx.x;
    const int w    = tid >> 5;
    const int lane = tid & 31;

    // row ownership: warps 0-3 -> left rows, 4-7 -> right rows
    const int hw    = w & 3;
    const int base0 = (w < 4) ? 0 : 50;
    const int nr    = (hw < 2) ? 13 : 12;   // rows d = base0 + hw + 4*t

    // ---------------- P0: biases; init counters ---------------------------
    if (tid < 64) { sb[tid] = bl1[tid]; sb[64 + tid] = br1[tid]; }
    if (tid < 20) { sb[128 + tid] = bl2[tid]; sb[148 + tid] = br2[tid];
                    sb[168 + tid] = bg[tid]; }
    if (tid < 100) scnt[tid] = 0;
    __syncthreads();

    // ---------------- P1: load edges -> regs, packed hemi/cross count -----
    int   myPk[8];
    float myW[8];
    {
        const size_t gbase = (size_t)g * EPG;
        const int    noff  = g * NPG;
        #pragma unroll
        for (int r = 0; r < 8; ++r) {
            int e = tid + 256 * r;
            if (e < EPG) {
                int ls = eidx[gbase + e] - noff;
                int ld = eidx[(size_t)Etot + gbase + e] - noff;
                float wv = ea[gbase + e];
                int hemi = ((ls < 50) == (ld < 50)) ? 1 : 0;
                myPk[r] = ls | (ld << 8) | (hemi << 16);
                myW[r]  = wv;
                atomicAdd(&scnt[ld], hemi ? 1 : 0x10000);
            } else {
                myPk[r] = -1; myW[r] = 0.f;
            }
        }
    }
    __syncthreads();

    // ---------------- P2: prefix sum over buckets (warp 0) ----------------
    if (w == 0) {
        int hc[4], tc[4];
        int tot = 0;
        #pragma unroll
        for (int i = 0; i < 4; ++i) {
            int b = lane * 4 + i;
            int v = (b < 100) ? scnt[b] : 0;
            hc[i] = v & 0xffff;
            tc[i] = hc[i] + (v >> 16);
            tot += tc[i];
        }
        int incl = tot;
        #pragma unroll
        for (int off = 1; off < 32; off <<= 1) {
            int v = __shfl_up_sync(0xffffffffu, incl, off);
            if (lane >= off) incl += v;
        }
        int run = incl - tot;   // exclusive prefix
        #pragma unroll
        for (int i = 0; i < 4; ++i) {
            int b = lane * 4 + i;
            if (b < 100) {
                sstart[b] = run;
                shend[b]  = run + hc[i];
                scurh[b]  = run;
                scurc[b]  = run + hc[i];
                run += tc[i];
            }
        }
        if (lane == 31) sstart[100] = run;
    }
    __syncthreads();

    // ---------------- P3: scatter edges (hemi first within bucket) --------
    #pragma unroll
    for (int r = 0; r < 8; ++r) {
        if (myPk[r] >= 0) {
            int ld = (myPk[r] >> 8) & 0xff;
            int* cur = (myPk[r] & (1 << 16)) ? scurh : scurc;
            int pos = atomicAdd(&cur[ld], 1);
            seA[pos] = myPk[r];
            seB[pos] = __float_as_int(myW[r]);
        }
    }
    __syncthreads();

    // ---------------- P4: degrees via bucket scan -> dinv -----------------
    if (tid < 100) {
        int s = sstart[tid], he = shend[tid], e1 = sstart[tid + 1];
        float dg1 = 1.f, dg3 = 1.f;
        for (int e = s; e < e1; ++e) {
            float wv = __int_as_float(seB[e]);
            dg3 += wv;
            if (e < he) dg1 += wv;
        }
        sdi1[tid] = rsqrtf(dg1);
        sdi3[tid] = rsqrtf(dg3);
    }
    __syncthreads();

    // ---------------- P5: per-edge norm precompute (packed 4B) ------------
    #pragma unroll
    for (int r = 0; r < 8; ++r) {
        int e = tid + 256 * r;
        if (e < EPG) {
            int pk = seA[e];
            float wv = __int_as_float(seB[e]);
            int ls = pk & 0xff;
            int ld = (pk >> 8) & 0xff;
            seB[e] = pack_ns(sdi3[ls] * wv * sdi3[ld], ls);
            if (pk & (1 << 16))
                seA[e] = pack_ns(sdi1[ls] * wv * sdi1[ld], ls);
        }
    }
    __syncthreads();

    // ---------------- P6: GEMM1  sh = x @ W(hemi)  [100,64] ---------------
    // f32x2 packed FMA, k-parity pairing; two row-groups (<=7 rows) to keep
    // accumulator pressure under the 85-reg cap at 3 CTAs/SM.
    {
        const float* Wb = (w < 4) ? Wl1 : Wr1;
        const float* xg = x + (size_t)g * NPG * 100;
        #pragma unroll
        for (int grp = 0; grp < 2; ++grp) {
            const int t0 = grp * 7;
            const int tcnt = (grp == 0) ? 7 : (nr - 7);   // 7 then 6 or 5
            unsigned long long accA[7], accB[7];
            #pragma unroll
            for (int r = 0; r < 7; ++r) { accA[r] = 0ull; accB[r] = 0ull; }
            for (int k = 0; k < 100; k += 2) {
                float wa0 = __ldg(Wb + k * 64 + lane);
                float wa1 = __ldg(Wb + (k + 1) * 64 + lane);
                float wb0 = __ldg(Wb + k * 64 + lane + 32);
                float wb1 = __ldg(Wb + (k + 1) * 64 + lane + 32);
                unsigned long long wA, wB;
                asm("mov.b64 %0,{%1,%2};" : "=l"(wA) : "f"(wa0), "f"(wa1));
                asm("mov.b64 %0,{%1,%2};" : "=l"(wB) : "f"(wb0), "f"(wb1));
                #pragma unroll
                for (int r = 0; r < 7; ++r) {
                    if (r < tcnt) {
                        int d = base0 + hw + 4 * (t0 + r);
                        unsigned long long xd =
                            __ldg((const unsigned long long*)(xg + d * 100 + k));
                        asm("fma.rn.f32x2 %0,%1,%2,%0;" : "+l"(accA[r]) : "l"(xd), "l"(wA));
                        asm("fma.rn.f32x2 %0,%1,%2,%0;" : "+l"(accB[r]) : "l"(xd), "l"(wB));
                    }
                }
            }
            #pragma unroll
            for (int r = 0; r < 7; ++r) {
                if (r < tcnt) {
                    int d = base0 + hw + 4 * (t0 + r);
                    float2 a = *(float2*)&accA[r];
                    float2 b = *(float2*)&accB[r];
                    sh[d * 64 + lane]      = a.x + a.y;
                    sh[d * 64 + lane + 32] = b.x + b.y;
                }
            }
        }
    }
    __syncthreads();

    // ---------------- P7: aggregate layer1 -> h1 (hemi edges only) --------
    for (int t = 0; t < nr; ++t) {
        int d = base0 + hw + 4 * t;
        float dv = sdi1[d];
        float self = dv * dv;
        float a0 = sh[d * 64 + lane] * self;
        float a1 = sh[d * 64 + lane + 32] * self;
        int e0 = sstart[d], e1 = shend[d];
        #pragma unroll 2
        for (int e = e0; e < e1; ++e) {
            int b = seA[e];                         // broadcast packed {nrm1,src}
            int ls = (b & 0x7F) << 6;               // src*64
            float nm = __int_as_float(b & ~0x7F);
            a0 = fmaf(sh[ls + lane],      nm, a0);
            a1 = fmaf(sh[ls + lane + 32], nm, a1);
        }
        int bb = (d < 50) ? 0 : 64;
        sh1[d * 64 + lane]      = lrelu(a0 + sb[bb + lane]);
        sh1[d * 64 + lane + 32] = lrelu(a1 + sb[bb + lane + 32]);
    }
    __syncthreads();

    // ---------------- P8: GEMM2  p2 = h1 @ W2(hemi)  [100,20] -------------
    // W2 read from global (L2-resident), chunk-hoisted to registers.
    if (lane < 20) {
        const float* W2 = (w < 4) ? Wl2 : Wr2;
        float acc[13];
        #pragma unroll
        for (int r = 0; r < 13; ++r) acc[r] = 0.f;
        for (int kc = 0; kc < 64; kc += 16) {
            float wreg[16];
            #pragma unroll
            for (int i = 0; i < 16; ++i) wreg[i] = __ldg(W2 + (kc + i) * 20 + lane);
            for (int t = 0; t < nr; ++t) {
                int d = base0 + hw + 4 * t;
                const float* hr = sh1 + d * 64 + kc;
                #pragma unroll
                for (int i = 0; i < 16; i += 4) {
                    float4 hv = *(const float4*)(hr + i);
                    acc[t] = fmaf(hv.x, wreg[i + 0], acc[t]);
                    acc[t] = fmaf(hv.y, wreg[i + 1], acc[t]);
                    acc[t] = fmaf(hv.z, wreg[i + 2], acc[t]);
                    acc[t] = fmaf(hv.w, wreg[i + 3], acc[t]);
                }
            }
        }
        for (int t = 0; t < nr; ++t) {
            int d = base0 + hw + 4 * t;
            p2[d * 20 + lane] = acc[t];
        }
    }
    __syncthreads();

    // ---------------- P9: aggregate layer2 -> h2 (hemi edges only) --------
    if (lane < 20) {
        for (int t = 0; t < nr; ++t) {
            int d = base0 + hw + 4 * t;
            float dv = sdi1[d];
            float a = p2[d * 20 + lane] * dv * dv;
            int e0 = sstart[d], e1 = shend[d];
            #pragma unroll 2
            for (int e = e0; e < e1; ++e) {
                int b = seA[e];
                int ls = b & 0x7F;
                float nm = __int_as_float(b & ~0x7F);
                a = fmaf(p2[ls * 20 + lane], nm, a);
            }
            int bb = (d < 50) ? 128 : 148;
            h2[d * 20 + lane] = lrelu(a + sb[bb + lane]);
        }
    }
    __syncthreads();

    // ---------------- P10: GEMM3  p3 = h2 @ Wg  [100,20] ------------------
    if (lane < 20) {
        float wg[20];
        #pragma unroll
        for (int k = 0; k < 20; ++k) wg[k] = __ldg(Wg + k * 20 + lane);
        for (int t = 0; t < nr; ++t) {
            int d = base0 + hw + 4 * t;
            float acc = 0.f;
            #pragma unroll
            for (int k = 0; k < 20; ++k)
                acc = fmaf(h2[d * 20 + k], wg[k], acc);
            p3[d * 20 + lane] = acc;
        }
    }
    __syncthreads();

    // ---------------- P11: aggregate layer3 (all edges) + pool ------------
    {
        float pool = 0.f;
        if (lane < 20) {
            for (int t = 0; t < nr; ++t) {
                int d = base0 + hw + 4 * t;
                float dv = sdi3[d];
                float a = p3[d * 20 + lane] * dv * dv;
                int e0 = sstart[d], e1 = sstart[d + 1];
                #pragma unroll 2
                for (int e = e0; e < e1; ++e) {
                    int b = seB[e];
                    int ls = b & 0x7F;
                    float nm = __int_as_float(b & ~0x7F);
                    a = fmaf(p3[ls * 20 + lane], nm, a);
                }
                pool += lrelu(a + sb[168 + lane]);
            }
            spart[w * 20 + lane] = pool;
        }
    }
    __syncthreads();

    if (tid < 20) {
        float s = 0.f;
        #pragma unroll
        for (int ww = 0; ww < 8; ++ww) s += spart[ww * 20 + tid];
        out[(size_t)g * 20 + tid] = s * 0.01f;   // mean over 100 nodes
    }
}

extern "C" void kernel_launch(void* const* d_in, const int* in_sizes, int n_in,
                              void* d_out, int out_size)
{
    (void)n_in;
    const long long Etot = (long long)in_sizes[1];   // total edges
    const int numGraphs = (int)(Etot / EPG);

    cudaFuncSetAttribute(gcn_fused_kernel,
                         cudaFuncAttributeMaxDynamicSharedMemorySize, SMEM_TOTAL);

    gcn_fused_kernel<<<numGraphs, 256, SMEM_TOTAL>>>(
        (const float*)d_in[0],  (const float*)d_in[1],
        (const float*)d_in[2],  (const float*)d_in[3],
        (const float*)d_in[4],  (const float*)d_in[5],
        (const float*)d_in[6],  (const float*)d_in[7],
        (const float*)d_in[8],  (const float*)d_in[9],
        (const float*)d_in[10], (const float*)d_in[11],
        (const int*)d_in[12], Etot,
        (float*)d_out);
    (void)out_size;
}

// round 8
// speedup vs baseline: 1.6755x; 1.0644x over previous
#include <cuda_runtime.h>

// Brain connectomic GCN: 2048 independent graphs x 100 nodes x 2000 edges.
// One CTA per graph, 3 CTAs/SM. Edges counting-sorted by dst (rank taken from
// the counting atomic's return value -> scatter needs NO atomics), hemi edges
// first per bucket, every segment padded to even length with zero-norm fillers
// so aggregation loops read edge PAIRS via one 8-byte broadcast.
// Per-edge norm packed into 4 bytes: fp32 norm with src in the low 7 mantissa
// bits (max 1.5e-5 relative perturbation; tolerance 1e-3).
//
//   h   = x @ (row<50 ? W_l1 : W_r1)           [100,64]  (f32x2 GEMM, x from gmem)
//   h1  = lrelu(agg_hemi(h) + b1)              [100,64]
//   p2  = h1 @ (row<50 ? W_l2 : W_r2)          [100,20]
//   h2  = lrelu(agg_hemi(p2) + b2)             [100,20]
//   p3  = h2 @ W_g1                            [100,20]
//   h3  = lrelu(agg_all(p3) + bg)              [100,20]
//   out[g] = mean_rows(h3)                     [20]
//
// agg(h)[d] = h[d]*dinv[d]^2 + sum_e nrm[e]*h[src[e]],  nrm = dinv[s]*w*dinv[d]
// deg[d] = 1 + sum of (masked) in-edge weights; dinv = rsqrt(deg).
// edge_index is int32 (JAX x64 disabled).

#define NPG 100
#define EPG 2000
#define EMAX 2208   // 2000 edges + <=2 pad slots per bucket, 8B-aligned

// ---- shared memory layout (bytes), total <= 72KB alloc ----
#define OFF_SH    0        // 6400 f : pre-agg h; later p2@0 / h2@2000 / p3@4000
#define OFF_SH1   25600    // 6400 f : h1
#define OFF_SEA   51200    // 2208 i32 : pk in sort; packed{nrm1,src} in hemi slots
#define OFF_SEB   60032    // 2208 i32 : w in sort; packed{nrm3,src} after
#define OFF_SB    68864    // 192 f : b1l[0..63] b1r[64..127] b2l@128 b2r@148 bg@168
#define OFF_CNT   69632    // 100 i32 packed: hemi count low16 | cross count high16
#define OFF_START 70032    // 101 i32 (+pad)
#define OFF_HEND  70448    // 100 i32 (padded hemi end = cross base)
#define OFF_DI1   70848    // 100 f
#define OFF_DI3   71248    // 100 f
#define OFF_PART  71648    // 160 f (8 warps x 20)
#define SMEM_TOTAL 72288
// NOTE: 72288 > 72K? 72288 bytes = 70.6KB. OK (alloc granularity 8KB -> 72KB? 72288<73728)

__device__ __forceinline__ float lrelu(float v) {
    return v > 0.f ? v : 0.01f * v;
}

// pack: fp32 norm with src (<128) replacing the low 7 mantissa bits
__device__ __forceinline__ int pack_ns(float nrm, int src) {
    return (__float_as_int(nrm) & ~0x7F) | src;
}

extern __shared__ char S[];

__global__ void __launch_bounds__(256, 3) gcn_fused_kernel(
    const float* __restrict__ x,   const float* __restrict__ ea,
    const float* __restrict__ Wl1, const float* __restrict__ bl1,
    const float* __restrict__ Wr1, const float* __restrict__ br1,
    const float* __restrict__ Wl2, const float* __restrict__ bl2,
    const float* __restrict__ Wr2, const float* __restrict__ br2,
    const float* __restrict__ Wg,  const float* __restrict__ bg,
    const int* __restrict__ eidx, long long Etot,
    float* __restrict__ out)
{
    float* sh   = (float*)(S + OFF_SH);
    float* sh1  = (float*)(S + OFF_SH1);
    int*   seA  = (int*)  (S + OFF_SEA);
    int*   seB  = (int*)  (S + OFF_SEB);
    float* sb   = (float*)(S + OFF_SB);
    int*   scnt = (int*)  (S + OFF_CNT);
    int*   sstart=(int*)  (S + OFF_START);
    int*   shend= (int*)  (S + OFF_HEND);
    float* sdi1 = (float*)(S + OFF_DI1);
    float* sdi3 = (float*)(S + OFF_DI3);
    float* spart= (float*)(S + OFF_PART);
    // aliases into the (dead after agg1) pre-agg region
    float* p2 = sh;          // 2000 f
    float* h2 = sh + 2000;   // 2000 f
    float* p3 = sh + 4000;   // 2000 f

    const int g    = blockIdx.x;
    const int tid  = threadIdx.x;
    const int w    = tid >> 5;
    const int lane = tid & 31;

    // row ownership: warps 0-3 -> left rows, 4-7 -> right rows
    const int hw    = w & 3;
    const int base0 = (w < 4) ? 0 : 50;
    const int nr    = (hw < 2) ? 13 : 12;   // rows d = base0 + hw + 4*t

    // ---------------- P0: biases; zero counters + edge arrays -------------
    if (tid < 64) { sb[tid] = bl1[tid]; sb[64 + tid] = br1[tid]; }
    if (tid < 20) { sb[128 + tid] = bl2[tid]; sb[148 + tid] = br2[tid];
                    sb[168 + tid] = bg[tid]; }
    if (tid < 100) scnt[tid] = 0;
    {   // zero seA+seB (pads must read as zero-norm edges)
        float4* z = (float4*)seA;          // seA,seB contiguous: 2*2208 i32
        for (int i = tid; i < (2 * EMAX) / 4; i += 256) z[i] = make_float4(0.f, 0.f, 0.f, 0.f);
    }
    __syncthreads();

    // ---------------- P1: load edges; count + capture rank ----------------
    // rank within (hemi|cross) sub-bucket comes from the atomic return value,
    // packed into pk bits [17:25).
    int   myPk[8];
    float myW[8];
    {
        const size_t gbase = (size_t)g * EPG;
        const int    noff  = g * NPG;
        #pragma unroll
        for (int r = 0; r < 8; ++r) {
            int e = tid + 256 * r;
            if (e < EPG) {
                int ls = eidx[gbase + e] - noff;
                int ld = eidx[(size_t)Etot + gbase + e] - noff;
                float wv = ea[gbase + e];
                int hemi = ((ls < 50) == (ld < 50)) ? 1 : 0;
                int old = atomicAdd(&scnt[ld], hemi ? 1 : 0x10000);
                int rank = hemi ? (old & 0xffff) : (old >> 16);
                myPk[r] = ls | (ld << 8) | (hemi << 16) | (rank << 17);
                myW[r]  = wv;
            } else {
                myPk[r] = -1; myW[r] = 0.f;
            }
        }
    }
    __syncthreads();

    // ---------------- P2: prefix sum over even-padded buckets (warp 0) ----
    if (w == 0) {
        int hp[4], cp[4];
        int tot = 0;
        #pragma unroll
        for (int i = 0; i < 4; ++i) {
            int b = lane * 4 + i;
            int v = (b < 100) ? scnt[b] : 0;
            hp[i] = ((v & 0xffff) + 1) & ~1;   // hemi segment padded even
            cp[i] = ((v >> 16) + 1) & ~1;      // cross segment padded even
            tot += hp[i] + cp[i];
        }
        int incl = tot;
        #pragma unroll
        for (int off = 1; off < 32; off <<= 1) {
            int v = __shfl_up_sync(0xffffffffu, incl, off);
            if (lane >= off) incl += v;
        }
        int run = incl - tot;   // exclusive prefix (even)
        #pragma unroll
        for (int i = 0; i < 4; ++i) {
            int b = lane * 4 + i;
            if (b < 100) {
                sstart[b] = run;
                shend[b]  = run + hp[i];        // padded hemi end = cross base
                run += hp[i] + cp[i];
            }
        }
        if (lane == 31) sstart[100] = run;
    }
    __syncthreads();

    // ---------------- P3: scatter (no atomics: pos = base + rank) ---------
    #pragma unroll
    for (int r = 0; r < 8; ++r) {
        int pk = myPk[r];
        if (pk >= 0) {
            int ld   = (pk >> 8) & 0xff;
            int rank = (pk >> 17) & 0xff;
            int pos  = ((pk & (1 << 16)) ? sstart[ld] : shend[ld]) + rank;
            seA[pos] = pk;
            seB[pos] = __float_as_int(myW[r]);
        }
    }
    __syncthreads();

    // ---------------- P4: degrees via bucket scan -> dinv (pads are 0) ----
    if (tid < 100) {
        int s = sstart[tid], he = shend[tid], e1 = sstart[tid + 1];
        float dg1 = 1.f, dg3 = 1.f;
        for (int e = s; e < e1; ++e) {
            float wv = __int_as_float(seB[e]);
            dg3 += wv;
            if (e < he) dg1 += wv;
        }
        sdi1[tid] = rsqrtf(dg1);
        sdi3[tid] = rsqrtf(dg3);
    }
    __syncthreads();

    // ---------------- P5: per-edge norm precompute (packed 4B) ------------
    // Pad slots: pk==0 -> hemi bit 0, w==0 -> seB becomes pack(0,0)==0; seA
    // stays 0. Zero-norm edges are exact no-ops downstream.
    {
        const int total = sstart[100];
        #pragma unroll
        for (int r = 0; r < 9; ++r) {
            int e = tid + 256 * r;
            if (e < total) {
                int pk = seA[e];
                float wv = __int_as_float(seB[e]);
                int ls = pk & 0xff;
                int ld = (pk >> 8) & 0xff;
                seB[e] = pack_ns(sdi3[ls] * wv * sdi3[ld], ls);
                if (pk & (1 << 16))
                    seA[e] = pack_ns(sdi1[ls] * wv * sdi1[ld], ls);
            }
        }
    }
    __syncthreads();

    // ---------------- P6: GEMM1  sh = x @ W(hemi)  [100,64] ---------------
    // f32x2 packed FMA, k-parity pairing; two row-groups (<=7 rows) to keep
    // accumulator pressure under the 85-reg cap at 3 CTAs/SM.
    {
        const float* Wb = (w < 4) ? Wl1 : Wr1;
        const float* xg = x + (size_t)g * NPG * 100;
        #pragma unroll
        for (int grp = 0; grp < 2; ++grp) {
            const int t0 = grp * 7;
            const int tcnt = (grp == 0) ? 7 : (nr - 7);   // 7 then 6 or 5
            unsigned long long accA[7], accB[7];
            #pragma unroll
            for (int r = 0; r < 7; ++r) { accA[r] = 0ull; accB[r] = 0ull; }
            for (int k = 0; k < 100; k += 2) {
                float wa0 = __ldg(Wb + k * 64 + lane);
                float wa1 = __ldg(Wb + (k + 1) * 64 + lane);
                float wb0 = __ldg(Wb + k * 64 + lane + 32);
                float wb1 = __ldg(Wb + (k + 1) * 64 + lane + 32);
                unsigned long long wA, wB;
                asm("mov.b64 %0,{%1,%2};" : "=l"(wA) : "f"(wa0), "f"(wa1));
                asm("mov.b64 %0,{%1,%2};" : "=l"(wB) : "f"(wb0), "f"(wb1));
                #pragma unroll
                for (int r = 0; r < 7; ++r) {
                    if (r < tcnt) {
                        int d = base0 + hw + 4 * (t0 + r);
                        unsigned long long xd =
                            __ldg((const unsigned long long*)(xg + d * 100 + k));
                        asm("fma.rn.f32x2 %0,%1,%2,%0;" : "+l"(accA[r]) : "l"(xd), "l"(wA));
                        asm("fma.rn.f32x2 %0,%1,%2,%0;" : "+l"(accB[r]) : "l"(xd), "l"(wB));
                    }
                }
            }
            #pragma unroll
            for (int r = 0; r < 7; ++r) {
                if (r < tcnt) {
                    int d = base0 + hw + 4 * (t0 + r);
                    float2 a = *(float2*)&accA[r];
                    float2 b = *(float2*)&accB[r];
                    sh[d * 64 + lane]      = a.x + a.y;
                    sh[d * 64 + lane + 32] = b.x + b.y;
                }
            }
        }
    }
    __syncthreads();

    // ---------------- P7: aggregate layer1 -> h1 (hemi, edge PAIRS) -------
    for (int t = 0; t < nr; ++t) {
        int d = base0 + hw + 4 * t;
        float dv = sdi1[d];
        float self = dv * dv;
        float a0 = sh[d * 64 + lane] * self;
        float a1 = sh[d * 64 + lane + 32] * self;
        int e0 = sstart[d], e1 = shend[d];        // both even
        for (int e = e0; e < e1; e += 2) {
            int2 b2 = *(const int2*)&seA[e];      // 8B broadcast: 2 packed edges
            int   ls0 = (b2.x & 0x7F) << 6;
            float nm0 = __int_as_float(b2.x & ~0x7F);
            int   ls1 = (b2.y & 0x7F) << 6;
            float nm1 = __int_as_float(b2.y & ~0x7F);
            a0 = fmaf(sh[ls0 + lane],      nm0, a0);
            a1 = fmaf(sh[ls0 + lane + 32], nm0, a1);
            a0 = fmaf(sh[ls1 + lane],      nm1, a0);
            a1 = fmaf(sh[ls1 + lane + 32], nm1, a1);
        }
        int bb = (d < 50) ? 0 : 64;
        sh1[d * 64 + lane]      = lrelu(a0 + sb[bb + lane]);
        sh1[d * 64 + lane + 32] = lrelu(a1 + sb[bb + lane + 32]);
    }
    __syncthreads();

    // ---------------- P8: GEMM2  p2 = h1 @ W2(hemi)  [100,20] -------------
    if (lane < 20) {
        const float* W2 = (w < 4) ? Wl2 : Wr2;
        float acc[13];
        #pragma unroll
        for (int r = 0; r < 13; ++r) acc[r] = 0.f;
        for (int kc = 0; kc < 64; kc += 16) {
            float wreg[16];
            #pragma unroll
            for (int i = 0; i < 16; ++i) wreg[i] = __ldg(W2 + (kc + i) * 20 + lane);
            for (int t = 0; t < nr; ++t) {
                int d = base0 + hw + 4 * t;
                const float* hr = sh1 + d * 64 + kc;
                #pragma unroll
                for (int i = 0; i < 16; i += 4) {
                    float4 hv = *(const float4*)(hr + i);
                    acc[t] = fmaf(hv.x, wreg[i + 0], acc[t]);
                    acc[t] = fmaf(hv.y, wreg[i + 1], acc[t]);
                    acc[t] = fmaf(hv.z, wreg[i + 2], acc[t]);
                    acc[t] = fmaf(hv.w, wreg[i + 3], acc[t]);
                }
            }
        }
        for (int t = 0; t < nr; ++t) {
            int d = base0 + hw + 4 * t;
            p2[d * 20 + lane] = acc[t];
        }
    }
    __syncthreads();

    // ---------------- P9: aggregate layer2 -> h2 (hemi, edge PAIRS) -------
    if (lane < 20) {
        for (int t = 0; t < nr; ++t) {
            int d = base0 + hw + 4 * t;
            float dv = sdi1[d];
            float a = p2[d * 20 + lane] * dv * dv;
            int e0 = sstart[d], e1 = shend[d];
            for (int e = e0; e < e1; e += 2) {
                int2 b2 = *(const int2*)&seA[e];
                a = fmaf(p2[(b2.x & 0x7F) * 20 + lane], __int_as_float(b2.x & ~0x7F), a);
                a = fmaf(p2[(b2.y & 0x7F) * 20 + lane], __int_as_float(b2.y & ~0x7F), a);
            }
            int bb = (d < 50) ? 128 : 148;
            h2[d * 20 + lane] = lrelu(a + sb[bb + lane]);
        }
    }
    __syncthreads();

    // ---------------- P10: GEMM3  p3 = h2 @ Wg  [100,20] ------------------
    if (lane < 20) {
        float wg[20];
        #pragma unroll
        for (int k = 0; k < 20; ++k) wg[k] = __ldg(Wg + k * 20 + lane);
        for (int t = 0; t < nr; ++t) {
            int d = base0 + hw + 4 * t;
            float acc = 0.f;
            #pragma unroll
            for (int k = 0; k < 20; ++k)
                acc = fmaf(h2[d * 20 + k], wg[k], acc);
            p3[d * 20 + lane] = acc;
        }
    }
    __syncthreads();

    // ---------------- P11: aggregate layer3 (all edges, PAIRS) + pool -----
    {
        float pool = 0.f;
        if (lane < 20) {
            for (int t = 0; t < nr; ++t) {
                int d = base0 + hw + 4 * t;
                float dv = sdi3[d];
                float a = p3[d * 20 + lane] * dv * dv;
                int e0 = sstart[d], e1 = sstart[d + 1];
                for (int e = e0; e < e1; e += 2) {
                    int2 b2 = *(const int2*)&seB[e];
                    a = fmaf(p3[(b2.x & 0x7F) * 20 + lane], __int_as_float(b2.x & ~0x7F), a);
                    a = fmaf(p3[(b2.y & 0x7F) * 20 + lane], __int_as_float(b2.y & ~0x7F), a);
                }
                pool += lrelu(a + sb[168 + lane]);
            }
            spart[w * 20 + lane] = pool;
        }
    }
    __syncthreads();

    if (tid < 20) {
        float s = 0.f;
        #pragma unroll
        for (int ww = 0; ww < 8; ++ww) s += spart[ww * 20 + tid];
        out[(size_t)g * 20 + tid] = s * 0.01f;   // mean over 100 nodes
    }
}

extern "C" void kernel_launch(void* const* d_in, const int* in_sizes, int n_in,
                              void* d_out, int out_size)
{
    (void)n_in;
    const long long Etot = (long long)in_sizes[1];   // total edges
    const int numGraphs = (int)(Etot / EPG);

    cudaFuncSetAttribute(gcn_fused_kernel,
                         cudaFuncAttributeMaxDynamicSharedMemorySize, SMEM_TOTAL);

    gcn_fused_kernel<<<numGraphs, 256, SMEM_TOTAL>>>(
        (const float*)d_in[0],  (const float*)d_in[1],
        (const float*)d_in[2],  (const float*)d_in[3],
        (const float*)d_in[4],  (const float*)d_in[5],
        (const float*)d_in[6],  (const float*)d_in[7],
        (const float*)d_in[8],  (const float*)d_in[9],
        (const float*)d_in[10], (const float*)d_in[11],
        (const int*)d_in[12], Etot,
        (float*)d_out);
    (void)out_size;
}